// round 11
// baseline (speedup 1.0000x reference)
#include <cuda_runtime.h>
#include <math.h>
#include <cstdint>

// ---------------------------------------------------------------------------
// NaN-interpolation, [1, 2M, 16] f32. element e -> column (e&15).
// reduce: 1184 blocks (8/SM, 64 warps), MLP2 register loads + L2 prefetch
//         running ahead (register-free DRAM MLP). Last block folds partials
//         into g_mean (ticket pattern) -- no separate finalize launch.
// fill:   unchanged from best config: reverse-order streaming, MLP=4.
// ---------------------------------------------------------------------------

#define COLS      16
#define NBLOCKS   (148 * 8)               // 1184, one wave at 8/SM
#define NTHREADS  256
#define STRIDE    (NBLOCKS * NTHREADS)    // 303104, multiple of 4

__device__ float g_part_sum[NBLOCKS][COLS];
__device__ float g_part_cnt[NBLOCKS][COLS];
__device__ float g_mean[COLS];
__device__ unsigned long long g_ticket;   // monotonic across graph replays

struct Acc { float s0, s1, s2, s3, c0, c1, c2, c3; };

static __device__ __forceinline__ void acc4(Acc& a, const float4& q) {
    bool v0 = (q.x == q.x), v1 = (q.y == q.y);
    bool v2 = (q.z == q.z), v3 = (q.w == q.w);
    a.s0 += v0 ? q.x : 0.0f;  a.c0 += v0 ? 1.0f : 0.0f;
    a.s1 += v1 ? q.y : 0.0f;  a.c1 += v1 ? 1.0f : 0.0f;
    a.s2 += v2 ? q.z : 0.0f;  a.c2 += v2 ? 1.0f : 0.0f;
    a.s3 += v3 ? q.w : 0.0f;  a.c3 += v3 ? 1.0f : 0.0f;
}

static __device__ __forceinline__ void prefetchL2(const float4* p) {
    asm volatile("prefetch.global.L2 [%0];" :: "l"(p));
}

__global__ void __launch_bounds__(NTHREADS, 8) interp_reduce_kernel(
    const float4* __restrict__ in, int n4)
{
    __shared__ float s_sum[COLS];
    __shared__ float s_cnt[COLS];
    __shared__ bool  s_last;

    const int t   = threadIdx.x;
    const int b   = blockIdx.x;
    const int idx = b * NTHREADS + t;
    const int g   = idx & 3;                 // column group (STRIDE % 4 == 0)

    if (t < COLS) { s_sum[t] = 0.0f; s_cnt[t] = 0.0f; }
    __syncthreads();

    Acc a = {0.f, 0.f, 0.f, 0.f, 0.f, 0.f, 0.f, 0.f};

    // Prime the L2 prefetch window (2 iterations = 4 strides ahead of consume).
    {
        int p0 = idx;               if (p0 >= n4) p0 = n4 - 1;
        int p1 = idx + STRIDE;      if (p1 >= n4) p1 = n4 - 1;
        int p2 = idx + 2 * STRIDE;  if (p2 >= n4) p2 = n4 - 1;
        int p3 = idx + 3 * STRIDE;  if (p3 >= n4) p3 = n4 - 1;
        prefetchL2(&in[p0]); prefetchL2(&in[p1]);
        prefetchL2(&in[p2]); prefetchL2(&in[p3]);
    }

    int v = idx;
    for (; v + STRIDE < n4; v += 2 * STRIDE) {
        // Prefetch 2 iterations ahead (register-free DRAM MLP).
        int p0 = v + 4 * STRIDE;  if (p0 >= n4) p0 = n4 - 1;
        int p1 = v + 5 * STRIDE;  if (p1 >= n4) p1 = n4 - 1;
        prefetchL2(&in[p0]);
        prefetchL2(&in[p1]);
        float4 q0 = in[v];
        float4 q1 = in[v + STRIDE];
        acc4(a, q0);
        acc4(a, q1);
    }
    for (; v < n4; v += STRIDE) {
        float4 q = in[v];
        acc4(a, q);
    }

    atomicAdd(&s_sum[4 * g + 0], a.s0);  atomicAdd(&s_cnt[4 * g + 0], a.c0);
    atomicAdd(&s_sum[4 * g + 1], a.s1);  atomicAdd(&s_cnt[4 * g + 1], a.c1);
    atomicAdd(&s_sum[4 * g + 2], a.s2);  atomicAdd(&s_cnt[4 * g + 2], a.c2);
    atomicAdd(&s_sum[4 * g + 3], a.s3);  atomicAdd(&s_cnt[4 * g + 3], a.c3);
    __syncthreads();

    if (t < COLS) {
        g_part_sum[b][t] = s_sum[t];
        g_part_cnt[b][t] = s_cnt[t];
    }

    // ---- last-block finalize (replaces the separate finalize launch) ----
    __threadfence();                         // partials visible before ticket
    if (t == 0) {
        unsigned long long old = atomicAdd(&g_ticket, 1ULL);
        s_last = ((old % NBLOCKS) == NBLOCKS - 1);
    }
    __syncthreads();

    if (s_last) {
        __threadfence();                     // see all blocks' partials
        __shared__ float sh_s[NTHREADS];
        __shared__ float sh_n[NTHREADS];
        const int c = t & 15;
        float S = 0.f, N = 0.f;
        for (int j = t >> 4; j < NBLOCKS; j += NTHREADS / 16) {  // 74 each
            S += g_part_sum[j][c];
            N += g_part_cnt[j][c];
        }
        sh_s[t] = S; sh_n[t] = N;
        __syncthreads();
        if (t < COLS) {
            float SS = 0.f, NN = 0.f;
            #pragma unroll
            for (int k = 0; k < NTHREADS / 16; k++) {
                SS += sh_s[k * 16 + t];
                NN += sh_n[k * 16 + t];
            }
            g_mean[t] = SS / fmaxf(NN, 1.0f);
        }
    }
}

static __device__ __forceinline__ float4 fill4(const float4& q,
                                               float m0, float m1,
                                               float m2, float m3) {
    float4 o;
    o.x = (q.x == q.x) ? q.x : m0;
    o.y = (q.y == q.y) ? q.y : m1;
    o.z = (q.z == q.z) ? q.z : m2;
    o.w = (q.w == q.w) ? q.w : m3;
    return o;
}

__global__ void __launch_bounds__(NTHREADS, 8) interp_fill_kernel(
    const float4* __restrict__ in, float4* __restrict__ out, int n4)
{
    const int t   = threadIdx.x;
    const int idx = blockIdx.x * NTHREADS + t;
    const int g   = idx & 3;

    const float m0 = g_mean[4 * g + 0];
    const float m1 = g_mean[4 * g + 1];
    const float m2 = g_mean[4 * g + 2];
    const float m3 = g_mean[4 * g + 3];

    if (idx >= n4) return;

    // Reverse grid-stride: start in the L2-resident tail left by the reduce.
    int v = idx + ((n4 - 1 - idx) / STRIDE) * STRIDE;

    for (; v - 3 * STRIDE >= 0; v -= 4 * STRIDE) {
        float4 q0 = __ldcs(&in[v]);
        float4 q1 = __ldcs(&in[v - STRIDE]);
        float4 q2 = __ldcs(&in[v - 2 * STRIDE]);
        float4 q3 = __ldcs(&in[v - 3 * STRIDE]);
        float4 o0 = fill4(q0, m0, m1, m2, m3);
        float4 o1 = fill4(q1, m0, m1, m2, m3);
        float4 o2 = fill4(q2, m0, m1, m2, m3);
        float4 o3 = fill4(q3, m0, m1, m2, m3);
        __stcs(&out[v],              o0);
        __stcs(&out[v - STRIDE],     o1);
        __stcs(&out[v - 2 * STRIDE], o2);
        __stcs(&out[v - 3 * STRIDE], o3);
    }
    for (; v >= 0; v -= STRIDE) {
        float4 q = __ldcs(&in[v]);
        __stcs(&out[v], fill4(q, m0, m1, m2, m3));
    }
}

extern "C" void kernel_launch(void* const* d_in, const int* in_sizes, int n_in,
                              void* d_out, int out_size)
{
    const float4* in  = (const float4*)d_in[0];
    float4*       out = (float4*)d_out;
    int n4 = in_sizes[0] / 4;   // 8,000,000 exact

    interp_reduce_kernel<<<NBLOCKS, NTHREADS>>>(in, n4);
    interp_fill_kernel<<<NBLOCKS, NTHREADS>>>(in, out, n4);
}

// round 12
// speedup vs baseline: 1.2871x; 1.2871x over previous
#include <cuda_runtime.h>
#include <math.h>

// ---------------------------------------------------------------------------
// NaN-interpolation, [1, 2M, 16] f32. element e -> column (e&15),
// float4 v -> columns 4*(v&3)..4*(v&3)+3.
// reduce: 592 blocks (4/SM, 64-reg budget), 12 front-batched L2-only loads
// finalize: fold partials -> means (1 block)
// fill: 1184 blocks, reverse-order streaming pass, MLP=4 (proven 37.8us)
// ---------------------------------------------------------------------------

#define COLS      16
#define RBLOCKS   (148 * 4)               // 592
#define FBLOCKS   (148 * 8)               // 1184
#define NTHREADS  256
#define RSTRIDE   (RBLOCKS * NTHREADS)    // 151552, multiple of 4
#define FSTRIDE   (FBLOCKS * NTHREADS)    // 303104, multiple of 4
#define MLP       12

__device__ float g_part_sum[RBLOCKS][COLS];
__device__ float g_part_cnt[RBLOCKS][COLS];
__device__ float g_mean[COLS];

struct Acc { float s0, s1, s2, s3, c0, c1, c2, c3; };

static __device__ __forceinline__ void acc4(Acc& a, const float4& q) {
    bool v0 = (q.x == q.x), v1 = (q.y == q.y);
    bool v2 = (q.z == q.z), v3 = (q.w == q.w);
    a.s0 += v0 ? q.x : 0.0f;  a.c0 += v0 ? 1.0f : 0.0f;
    a.s1 += v1 ? q.y : 0.0f;  a.c1 += v1 ? 1.0f : 0.0f;
    a.s2 += v2 ? q.z : 0.0f;  a.c2 += v2 ? 1.0f : 0.0f;
    a.s3 += v3 ? q.w : 0.0f;  a.c3 += v3 ? 1.0f : 0.0f;
}

__global__ void __launch_bounds__(NTHREADS, 4) interp_reduce_kernel(
    const float4* __restrict__ in, int n4)
{
    __shared__ float s_sum[COLS];
    __shared__ float s_cnt[COLS];
    const int t   = threadIdx.x;
    const int idx = blockIdx.x * NTHREADS + t;
    const int g   = idx & 3;                 // constant column group

    if (t < COLS) { s_sum[t] = 0.0f; s_cnt[t] = 0.0f; }
    __syncthreads();

    Acc a = {0.f, 0.f, 0.f, 0.f, 0.f, 0.f, 0.f, 0.f};

    int v = idx;
    // 12 front-batched L2-only (ldcg) loads: 196 KB in flight per SM.
    for (; v + (MLP - 1) * RSTRIDE < n4; v += MLP * RSTRIDE) {
        float4 q[MLP];
        #pragma unroll
        for (int j = 0; j < MLP; j++) q[j] = __ldcg(&in[v + j * RSTRIDE]);
        #pragma unroll
        for (int j = 0; j < MLP; j++) acc4(a, q[j]);
    }
    for (; v < n4; v += RSTRIDE) {
        float4 q = __ldcg(&in[v]);
        acc4(a, q);
    }

    atomicAdd(&s_sum[4 * g + 0], a.s0);  atomicAdd(&s_cnt[4 * g + 0], a.c0);
    atomicAdd(&s_sum[4 * g + 1], a.s1);  atomicAdd(&s_cnt[4 * g + 1], a.c1);
    atomicAdd(&s_sum[4 * g + 2], a.s2);  atomicAdd(&s_cnt[4 * g + 2], a.c2);
    atomicAdd(&s_sum[4 * g + 3], a.s3);  atomicAdd(&s_cnt[4 * g + 3], a.c3);
    __syncthreads();

    if (t < COLS) {
        g_part_sum[blockIdx.x][t] = s_sum[t];
        g_part_cnt[blockIdx.x][t] = s_cnt[t];
    }
}

__global__ void __launch_bounds__(NTHREADS) interp_finalize_kernel() {
    __shared__ float sh_s[NTHREADS];
    __shared__ float sh_n[NTHREADS];
    const int t = threadIdx.x;
    const int c = t & 15;
    float S = 0.f, N = 0.f;
    for (int j = t >> 4; j < RBLOCKS; j += NTHREADS / 16) {   // 37 each
        S += g_part_sum[j][c];
        N += g_part_cnt[j][c];
    }
    sh_s[t] = S; sh_n[t] = N;
    __syncthreads();
    if (t < COLS) {
        float SS = 0.f, NN = 0.f;
        #pragma unroll
        for (int k = 0; k < NTHREADS / 16; k++) {
            SS += sh_s[k * 16 + t];
            NN += sh_n[k * 16 + t];
        }
        g_mean[t] = SS / fmaxf(NN, 1.0f);
    }
}

// ---- fill: exact R1 configuration (37.8 us measured) ----
__global__ void __launch_bounds__(NTHREADS) interp_fill_kernel(
    const float4* __restrict__ in, float4* __restrict__ out, int n4)
{
    const int t   = threadIdx.x;
    const int idx = blockIdx.x * NTHREADS + t;
    const int g   = idx & 3;

    const float m0 = g_mean[4 * g + 0];
    const float m1 = g_mean[4 * g + 1];
    const float m2 = g_mean[4 * g + 2];
    const float m3 = g_mean[4 * g + 3];

    // Reverse grid-stride: start in the L2-resident tail left by the reduce.
    if (idx < n4) {
        int v = idx + ((n4 - 1 - idx) / FSTRIDE) * FSTRIDE;
        for (; v >= 0; v -= FSTRIDE) {
            float4 x = __ldcs(&in[v]);
            float4 o;
            o.x = (x.x == x.x) ? x.x : m0;
            o.y = (x.y == x.y) ? x.y : m1;
            o.z = (x.z == x.z) ? x.z : m2;
            o.w = (x.w == x.w) ? x.w : m3;
            __stcs(&out[v], o);
        }
    }
}

extern "C" void kernel_launch(void* const* d_in, const int* in_sizes, int n_in,
                              void* d_out, int out_size)
{
    const float4* in  = (const float4*)d_in[0];
    float4*       out = (float4*)d_out;
    int n4 = in_sizes[0] / 4;   // 8,000,000 exact

    interp_reduce_kernel<<<RBLOCKS, NTHREADS>>>(in, n4);
    interp_finalize_kernel<<<1, NTHREADS>>>();
    interp_fill_kernel<<<FBLOCKS, NTHREADS>>>(in, out, n4);
}

// round 13
// speedup vs baseline: 1.5531x; 1.2066x over previous
#include <cuda_runtime.h>
#include <math.h>
#include <cstdint>

// ---------------------------------------------------------------------------
// NaN-interpolation, [1, 2M, 16] f32. element e -> column (e&15).
// reduce: per-warp cp.async.cg (LDGSTS) 3-stage ring into smem. No barriers,
//         no mbarriers: wait_group only (per-thread). 444 blocks (3/SM),
//         72KB dyn smem/block -> 216KB in flight per SM, ~35 regs.
// finalize: fold partials -> means (1 block).
// fill: proven reverse-order streaming pass (37.8 us).
// ---------------------------------------------------------------------------

#define COLS      16
#define NTHREADS  256
#define WPB       8                         // warps per block
#define RBLOCKS   (148 * 3)                 // 444
#define NW        (RBLOCKS * WPB)           // 3552 warps
#define U         6                         // float4 per lane per stage
#define STAGES    3
#define TILE      (32 * U)                  // 192 float4 per warp-stage
#define SMEM_BYTES (WPB * STAGES * U * 32 * 16)   // 73728

#define FBLOCKS   (148 * 8)                 // 1184
#define FSTRIDE   (FBLOCKS * NTHREADS)      // 303104

__device__ float g_part_sum[RBLOCKS][COLS];
__device__ float g_part_cnt[RBLOCKS][COLS];
__device__ float g_mean[COLS];

struct Acc { float s0, s1, s2, s3, c0, c1, c2, c3; };

static __device__ __forceinline__ void acc4(Acc& a, const float4& q) {
    bool v0 = (q.x == q.x), v1 = (q.y == q.y);
    bool v2 = (q.z == q.z), v3 = (q.w == q.w);
    a.s0 += v0 ? q.x : 0.0f;  a.c0 += v0 ? 1.0f : 0.0f;
    a.s1 += v1 ? q.y : 0.0f;  a.c1 += v1 ? 1.0f : 0.0f;
    a.s2 += v2 ? q.z : 0.0f;  a.c2 += v2 ? 1.0f : 0.0f;
    a.s3 += v3 ? q.w : 0.0f;  a.c3 += v3 ? 1.0f : 0.0f;
}

static __device__ __forceinline__ void cp16(uint32_t s_dst, const void* g_src) {
    asm volatile("cp.async.cg.shared.global [%0], [%1], 16;"
                 :: "r"(s_dst), "l"(g_src) : "memory");
}
static __device__ __forceinline__ void cp_commit() {
    asm volatile("cp.async.commit_group;" ::: "memory");
}
template <int N>
static __device__ __forceinline__ void cp_wait() {
    asm volatile("cp.async.wait_group %0;" :: "n"(N) : "memory");
}

__global__ void __launch_bounds__(NTHREADS) interp_reduce_kernel(
    const float4* __restrict__ in, int n4)
{
    extern __shared__ float4 smem[];        // [WPB][STAGES][U][32]
    __shared__ float s_sum[COLS];
    __shared__ float s_cnt[COLS];

    const int t    = threadIdx.x;
    const int b    = blockIdx.x;
    const int lane = t & 31;
    const int wloc = t >> 5;
    const int W    = b * WPB + wloc;        // global warp id
    const int g    = lane & 3;              // column group (tile base ≡ 0 mod 4)

    if (t < COLS) { s_sum[t] = 0.0f; s_cnt[t] = 0.0f; }
    __syncthreads();

    const uint32_t smem_base = (uint32_t)__cvta_generic_to_shared(smem);
    const int ntiles = n4 / TILE;
    const int cnt = (W < ntiles) ? (ntiles - 1 - W) / NW + 1 : 0;

    // Issue stage k (guarded) + always commit (uniform group accounting).
    auto issue = [&](int k) {
        int tile = W + k * NW;
        if (tile < ntiles) {
            const float4* gp = in + (size_t)tile * TILE + lane;
            uint32_t sb = smem_base +
                (uint32_t)((((wloc * STAGES + (k % STAGES)) * U) * 32 + lane) * 16);
            #pragma unroll
            for (int j = 0; j < U; j++) cp16(sb + j * 512u, gp + j * 32);
        }
        cp_commit();
    };

    // Prime STAGES groups.
    issue(0); issue(1); issue(2);

    Acc a = {0.f, 0.f, 0.f, 0.f, 0.f, 0.f, 0.f, 0.f};

    for (int k = 0; k < cnt; k++) {
        cp_wait<STAGES - 1>();              // oldest group complete
        const int s = k % STAGES;
        const float4* sp = smem + ((wloc * STAGES + s) * U) * 32 + lane;
        #pragma unroll
        for (int j = 0; j < U; j++) {
            float4 q = sp[j * 32];
            acc4(a, q);
        }
        issue(k + STAGES);
    }
    cp_wait<0>();                            // drain (trailing empty/overflow groups)

    // Global remainder (n4 % TILE, < 192 f4): block 0 warp 0 via direct LDG.
    if (b == 0 && wloc == 0) {
        for (int f = ntiles * TILE + lane; f < n4; f += 32) {
            float4 q = in[f];
            acc4(a, q);                      // f ≡ lane (mod 4): same g mapping
        }
    }

    atomicAdd(&s_sum[4 * g + 0], a.s0);  atomicAdd(&s_cnt[4 * g + 0], a.c0);
    atomicAdd(&s_sum[4 * g + 1], a.s1);  atomicAdd(&s_cnt[4 * g + 1], a.c1);
    atomicAdd(&s_sum[4 * g + 2], a.s2);  atomicAdd(&s_cnt[4 * g + 2], a.c2);
    atomicAdd(&s_sum[4 * g + 3], a.s3);  atomicAdd(&s_cnt[4 * g + 3], a.c3);
    __syncthreads();

    if (t < COLS) {
        g_part_sum[b][t] = s_sum[t];
        g_part_cnt[b][t] = s_cnt[t];
    }
}

__global__ void __launch_bounds__(NTHREADS) interp_finalize_kernel() {
    __shared__ float sh_s[NTHREADS];
    __shared__ float sh_n[NTHREADS];
    const int t = threadIdx.x;
    const int c = t & 15;
    float S = 0.f, N = 0.f;
    for (int j = t >> 4; j < RBLOCKS; j += NTHREADS / 16) {
        S += g_part_sum[j][c];
        N += g_part_cnt[j][c];
    }
    sh_s[t] = S; sh_n[t] = N;
    __syncthreads();
    if (t < COLS) {
        float SS = 0.f, NN = 0.f;
        #pragma unroll
        for (int k = 0; k < NTHREADS / 16; k++) {
            SS += sh_s[k * 16 + t];
            NN += sh_n[k * 16 + t];
        }
        g_mean[t] = SS / fmaxf(NN, 1.0f);
    }
}

// ---- fill: proven R1 configuration (37.8 us) ----
__global__ void __launch_bounds__(NTHREADS) interp_fill_kernel(
    const float4* __restrict__ in, float4* __restrict__ out, int n4)
{
    const int t   = threadIdx.x;
    const int idx = blockIdx.x * NTHREADS + t;
    const int g   = idx & 3;

    const float m0 = g_mean[4 * g + 0];
    const float m1 = g_mean[4 * g + 1];
    const float m2 = g_mean[4 * g + 2];
    const float m3 = g_mean[4 * g + 3];

    if (idx < n4) {
        // Reverse grid-stride: start in the L2-resident tail left by the reduce.
        int v = idx + ((n4 - 1 - idx) / FSTRIDE) * FSTRIDE;
        for (; v >= 0; v -= FSTRIDE) {
            float4 x = __ldcs(&in[v]);
            float4 o;
            o.x = (x.x == x.x) ? x.x : m0;
            o.y = (x.y == x.y) ? x.y : m1;
            o.z = (x.z == x.z) ? x.z : m2;
            o.w = (x.w == x.w) ? x.w : m3;
            __stcs(&out[v], o);
        }
    }
}

extern "C" void kernel_launch(void* const* d_in, const int* in_sizes, int n_in,
                              void* d_out, int out_size)
{
    const float4* in  = (const float4*)d_in[0];
    float4*       out = (float4*)d_out;
    int n4 = in_sizes[0] / 4;   // 8,000,000 exact

    cudaFuncSetAttribute(interp_reduce_kernel,
                         cudaFuncAttributeMaxDynamicSharedMemorySize, SMEM_BYTES);
    interp_reduce_kernel<<<RBLOCKS, NTHREADS, SMEM_BYTES>>>(in, n4);
    interp_finalize_kernel<<<1, NTHREADS>>>();
    interp_fill_kernel<<<FBLOCKS, NTHREADS>>>(in, out, n4);
}

// round 14
// speedup vs baseline: 1.5764x; 1.0150x over previous
#include <cuda_runtime.h>
#include <math.h>

// ---------------------------------------------------------------------------
// NaN-interpolation, [1, 2M, 16] f32. element e -> column (e&15),
// float4 v -> columns 4*(v&3)..4*(v&3)+3.
// reduce: R5 exact config (592 blocks, 4/SM, 64-reg budget, MLP=8) — sits at
//         the measured ~4.2 TB/s read-only path cap.
// finalize: fold partials -> means (1 block).
// fill: NEW — same 4/SM + MLP=8 recipe applied to the read side, reverse
//       order + streaming ld/st kept for L2 tail reuse.
// ---------------------------------------------------------------------------

#define COLS      16
#define RBLOCKS   (148 * 4)               // 592
#define NTHREADS  256
#define RSTRIDE   (RBLOCKS * NTHREADS)    // 151552, multiple of 4

__device__ float g_part_sum[RBLOCKS][COLS];
__device__ float g_part_cnt[RBLOCKS][COLS];
__device__ float g_mean[COLS];

struct Acc { float s0, s1, s2, s3, c0, c1, c2, c3; };

static __device__ __forceinline__ void acc4(Acc& a, const float4& q) {
    bool v0 = (q.x == q.x), v1 = (q.y == q.y);
    bool v2 = (q.z == q.z), v3 = (q.w == q.w);
    a.s0 += v0 ? q.x : 0.0f;  a.c0 += v0 ? 1.0f : 0.0f;
    a.s1 += v1 ? q.y : 0.0f;  a.c1 += v1 ? 1.0f : 0.0f;
    a.s2 += v2 ? q.z : 0.0f;  a.c2 += v2 ? 1.0f : 0.0f;
    a.s3 += v3 ? q.w : 0.0f;  a.c3 += v3 ? 1.0f : 0.0f;
}

__global__ void __launch_bounds__(NTHREADS, 4) interp_reduce_kernel(
    const float4* __restrict__ in, int n4)
{
    __shared__ float s_sum[COLS];
    __shared__ float s_cnt[COLS];
    const int t   = threadIdx.x;
    const int idx = blockIdx.x * NTHREADS + t;
    const int g   = idx & 3;                 // constant column group

    if (t < COLS) { s_sum[t] = 0.0f; s_cnt[t] = 0.0f; }
    __syncthreads();

    Acc a = {0.f, 0.f, 0.f, 0.f, 0.f, 0.f, 0.f, 0.f};

    int v = idx;
    // 8 independent front-batched LDG.128s (MLP=8) — measured 4.22 TB/s.
    for (; v + 7 * RSTRIDE < n4; v += 8 * RSTRIDE) {
        float4 q0 = in[v];
        float4 q1 = in[v + 1 * RSTRIDE];
        float4 q2 = in[v + 2 * RSTRIDE];
        float4 q3 = in[v + 3 * RSTRIDE];
        float4 q4 = in[v + 4 * RSTRIDE];
        float4 q5 = in[v + 5 * RSTRIDE];
        float4 q6 = in[v + 6 * RSTRIDE];
        float4 q7 = in[v + 7 * RSTRIDE];
        acc4(a, q0); acc4(a, q1); acc4(a, q2); acc4(a, q3);
        acc4(a, q4); acc4(a, q5); acc4(a, q6); acc4(a, q7);
    }
    for (; v < n4; v += RSTRIDE) {
        float4 q = in[v];
        acc4(a, q);
    }

    atomicAdd(&s_sum[4 * g + 0], a.s0);  atomicAdd(&s_cnt[4 * g + 0], a.c0);
    atomicAdd(&s_sum[4 * g + 1], a.s1);  atomicAdd(&s_cnt[4 * g + 1], a.c1);
    atomicAdd(&s_sum[4 * g + 2], a.s2);  atomicAdd(&s_cnt[4 * g + 2], a.c2);
    atomicAdd(&s_sum[4 * g + 3], a.s3);  atomicAdd(&s_cnt[4 * g + 3], a.c3);
    __syncthreads();

    if (t < COLS) {
        g_part_sum[blockIdx.x][t] = s_sum[t];
        g_part_cnt[blockIdx.x][t] = s_cnt[t];
    }
}

__global__ void __launch_bounds__(NTHREADS) interp_finalize_kernel() {
    __shared__ float sh_s[NTHREADS];
    __shared__ float sh_n[NTHREADS];
    const int t = threadIdx.x;
    const int c = t & 15;
    float S = 0.f, N = 0.f;
    for (int j = t >> 4; j < RBLOCKS; j += NTHREADS / 16) {   // 37 each
        S += g_part_sum[j][c];
        N += g_part_cnt[j][c];
    }
    sh_s[t] = S; sh_n[t] = N;
    __syncthreads();
    if (t < COLS) {
        float SS = 0.f, NN = 0.f;
        #pragma unroll
        for (int k = 0; k < NTHREADS / 16; k++) {
            SS += sh_s[k * 16 + t];
            NN += sh_n[k * 16 + t];
        }
        g_mean[t] = SS / fmaxf(NN, 1.0f);
    }
}

static __device__ __forceinline__ float4 fill4(const float4& q,
                                               float m0, float m1,
                                               float m2, float m3) {
    float4 o;
    o.x = (q.x == q.x) ? q.x : m0;
    o.y = (q.y == q.y) ? q.y : m1;
    o.z = (q.z == q.z) ? q.z : m2;
    o.w = (q.w == q.w) ? q.w : m3;
    return o;
}

// Fill with the R5 recipe: 4 blocks/SM, 64-reg budget, 8 front-batched loads.
__global__ void __launch_bounds__(NTHREADS, 4) interp_fill_kernel(
    const float4* __restrict__ in, float4* __restrict__ out, int n4)
{
    const int t   = threadIdx.x;
    const int idx = blockIdx.x * NTHREADS + t;
    const int g   = idx & 3;

    const float m0 = g_mean[4 * g + 0];
    const float m1 = g_mean[4 * g + 1];
    const float m2 = g_mean[4 * g + 2];
    const float m3 = g_mean[4 * g + 3];

    if (idx >= n4) return;

    // Reverse grid-stride: start in the L2-resident tail left by the reduce.
    int v = idx + ((n4 - 1 - idx) / RSTRIDE) * RSTRIDE;   // largest v ≡ idx

    for (; v - 7 * RSTRIDE >= 0; v -= 8 * RSTRIDE) {
        float4 q0 = __ldcs(&in[v]);
        float4 q1 = __ldcs(&in[v - 1 * RSTRIDE]);
        float4 q2 = __ldcs(&in[v - 2 * RSTRIDE]);
        float4 q3 = __ldcs(&in[v - 3 * RSTRIDE]);
        float4 q4 = __ldcs(&in[v - 4 * RSTRIDE]);
        float4 q5 = __ldcs(&in[v - 5 * RSTRIDE]);
        float4 q6 = __ldcs(&in[v - 6 * RSTRIDE]);
        float4 q7 = __ldcs(&in[v - 7 * RSTRIDE]);
        __stcs(&out[v],               fill4(q0, m0, m1, m2, m3));
        __stcs(&out[v - 1 * RSTRIDE], fill4(q1, m0, m1, m2, m3));
        __stcs(&out[v - 2 * RSTRIDE], fill4(q2, m0, m1, m2, m3));
        __stcs(&out[v - 3 * RSTRIDE], fill4(q3, m0, m1, m2, m3));
        __stcs(&out[v - 4 * RSTRIDE], fill4(q4, m0, m1, m2, m3));
        __stcs(&out[v - 5 * RSTRIDE], fill4(q5, m0, m1, m2, m3));
        __stcs(&out[v - 6 * RSTRIDE], fill4(q6, m0, m1, m2, m3));
        __stcs(&out[v - 7 * RSTRIDE], fill4(q7, m0, m1, m2, m3));
    }
    for (; v >= 0; v -= RSTRIDE) {
        float4 q = __ldcs(&in[v]);
        __stcs(&out[v], fill4(q, m0, m1, m2, m3));
    }
}

extern "C" void kernel_launch(void* const* d_in, const int* in_sizes, int n_in,
                              void* d_out, int out_size)
{
    const float4* in  = (const float4*)d_in[0];
    float4*       out = (float4*)d_out;
    int n4 = in_sizes[0] / 4;   // 8,000,000 exact

    interp_reduce_kernel<<<RBLOCKS, NTHREADS>>>(in, n4);
    interp_finalize_kernel<<<1, NTHREADS>>>();
    interp_fill_kernel<<<RBLOCKS, NTHREADS>>>(in, out, n4);
}